// round 14
// baseline (speedup 1.0000x reference)
#include <cuda_runtime.h>

// Problem constants (fixed shapes from reference)
#define BATCH 64
#define HEADS 128
#define SEQ   4096
#define DIM   512
#define PEDIM 64

// 1/sqrt(576) = 1/24
#define SM_SCALE 0.041666666666666664f

// Scratch for scores/probs: 64*128*4096 floats = 128 MB (static device array,
// allowed per harness rules; cudaMalloc is not).
__device__ float g_scores[(size_t)BATCH * HEADS * SEQ];

// ---------------------------------------------------------------------------
// Kernel 1: scores[b,h,s] = Q[b,h,:]·KV[b,s,:] + Qpe[b,h,:]·Kpe[b,s,:]
// GEMM NT per batch: M=128 (heads), N=4096 (seq), K=576 (512 + 64).
// Tile: BM=128, BN=128, BK=16; 256 threads; 8x8 micro-tile per thread.
// ---------------------------------------------------------------------------
__global__ __launch_bounds__(256, 2) void qk_kernel(
    const float* __restrict__ Q,
    const float* __restrict__ Qpe,
    const float* __restrict__ KV,
    const float* __restrict__ Kpe)
{
    __shared__ float As[16][132];  // [k][m], padded
    __shared__ float Bs[16][132];  // [k][n], padded

    const int b   = blockIdx.z;
    const int n0  = blockIdx.x * 128;
    const int tid = threadIdx.x;

    const float* Aq  = Q   + (size_t)b * HEADS * DIM;
    const float* Ap  = Qpe + (size_t)b * HEADS * PEDIM;
    const float* Bk  = KV  + (size_t)b * SEQ * DIM;
    const float* Bp  = Kpe + (size_t)b * SEQ * PEDIM;

    float acc[8][8];
#pragma unroll
    for (int i = 0; i < 8; i++)
#pragma unroll
        for (int j = 0; j < 8; j++) acc[i][j] = 0.0f;

    const int tm = (tid / 16) * 8;
    const int tn = (tid % 16) * 8;

#pragma unroll 1
    for (int phase = 0; phase < 2; phase++) {
        const float* Aptr = phase ? Ap : Aq;
        const float* Bptr = phase ? Bp : Bk;
        const int kdim = phase ? PEDIM : DIM;

#pragma unroll 1
        for (int k0 = 0; k0 < kdim; k0 += 16) {
            // Load A tile: 128 rows x 16 k (k contiguous). 512 float4, 2/thread.
#pragma unroll
            for (int l = 0; l < 2; l++) {
                int idx = tid + l * 256;
                int row = idx >> 2;
                int c4  = (idx & 3) * 4;
                float4 v = *reinterpret_cast<const float4*>(
                    Aptr + (size_t)row * kdim + k0 + c4);
                As[c4 + 0][row] = v.x;
                As[c4 + 1][row] = v.y;
                As[c4 + 2][row] = v.z;
                As[c4 + 3][row] = v.w;
            }
            // Load B tile: 128 rows (seq) x 16 k (k contiguous).
#pragma unroll
            for (int l = 0; l < 2; l++) {
                int idx = tid + l * 256;
                int row = idx >> 2;
                int c4  = (idx & 3) * 4;
                float4 v = *reinterpret_cast<const float4*>(
                    Bptr + (size_t)(n0 + row) * kdim + k0 + c4);
                Bs[c4 + 0][row] = v.x;
                Bs[c4 + 1][row] = v.y;
                Bs[c4 + 2][row] = v.z;
                Bs[c4 + 3][row] = v.w;
            }
            __syncthreads();

#pragma unroll
            for (int k = 0; k < 16; k++) {
                float a[8], bb[8];
                *reinterpret_cast<float4*>(a)      = *reinterpret_cast<const float4*>(&As[k][tm]);
                *reinterpret_cast<float4*>(a + 4)  = *reinterpret_cast<const float4*>(&As[k][tm + 4]);
                *reinterpret_cast<float4*>(bb)     = *reinterpret_cast<const float4*>(&Bs[k][tn]);
                *reinterpret_cast<float4*>(bb + 4) = *reinterpret_cast<const float4*>(&Bs[k][tn + 4]);
#pragma unroll
                for (int i = 0; i < 8; i++)
#pragma unroll
                    for (int j = 0; j < 8; j++)
                        acc[i][j] = fmaf(a[i], bb[j], acc[i][j]);
            }
            __syncthreads();
        }
    }

    float* out = g_scores + (size_t)b * HEADS * SEQ;
#pragma unroll
    for (int i = 0; i < 8; i++) {
        float* r = out + (size_t)(tm + i) * SEQ + n0 + tn;
        *reinterpret_cast<float4*>(r)     = make_float4(acc[i][0], acc[i][1], acc[i][2], acc[i][3]);
        *reinterpret_cast<float4*>(r + 4) = make_float4(acc[i][4], acc[i][5], acc[i][6], acc[i][7]);
    }
}

// ---------------------------------------------------------------------------
// Kernel 2: in-place row softmax over SEQ (with scale), one block per (b,h).
// Each thread holds 16 values in registers: single read + single write.
// ---------------------------------------------------------------------------
__global__ __launch_bounds__(256) void softmax_kernel()
{
    const size_t row = blockIdx.x;  // b*HEADS + h
    float* p = g_scores + row * SEQ;
    const int tid = threadIdx.x;

    float4 v[4];
#pragma unroll
    for (int it = 0; it < 4; it++)
        v[it] = *reinterpret_cast<const float4*>(p + tid * 4 + it * 1024);

    // --- max ---
    float m = -1e30f;
#pragma unroll
    for (int it = 0; it < 4; it++)
        m = fmaxf(m, fmaxf(fmaxf(v[it].x, v[it].y), fmaxf(v[it].z, v[it].w)));
#pragma unroll
    for (int o = 16; o > 0; o >>= 1)
        m = fmaxf(m, __shfl_xor_sync(0xffffffffu, m, o));

    __shared__ float red[8];
    if ((tid & 31) == 0) red[tid >> 5] = m;
    __syncthreads();
    m = red[0];
#pragma unroll
    for (int i = 1; i < 8; i++) m = fmaxf(m, red[i]);
    __syncthreads();

    // --- exp + sum ---
    float sum = 0.0f;
#pragma unroll
    for (int it = 0; it < 4; it++) {
        v[it].x = expf((v[it].x - m) * SM_SCALE);
        v[it].y = expf((v[it].y - m) * SM_SCALE);
        v[it].z = expf((v[it].z - m) * SM_SCALE);
        v[it].w = expf((v[it].w - m) * SM_SCALE);
        sum += v[it].x + v[it].y + v[it].z + v[it].w;
    }
#pragma unroll
    for (int o = 16; o > 0; o >>= 1)
        sum += __shfl_xor_sync(0xffffffffu, sum, o);

    __shared__ float red2[8];
    if ((tid & 31) == 0) red2[tid >> 5] = sum;
    __syncthreads();
    sum = red2[0];
#pragma unroll
    for (int i = 1; i < 8; i++) sum += red2[i];

    const float inv = 1.0f / sum;
#pragma unroll
    for (int it = 0; it < 4; it++) {
        v[it].x *= inv; v[it].y *= inv; v[it].z *= inv; v[it].w *= inv;
        *reinterpret_cast<float4*>(p + tid * 4 + it * 1024) = v[it];
    }
}

// ---------------------------------------------------------------------------
// Kernel 3: out[b,h,d] = sum_s P[b,h,s] * KV[b,s,d]
// GEMM NN per batch: M=128 (heads), N=512 (dim), K=4096 (seq).
// Same tiling: BM=128, BN=128, BK=16; 256 threads; 8x8 micro-tile.
// ---------------------------------------------------------------------------
__global__ __launch_bounds__(256, 2) void pv_kernel(
    const float* __restrict__ KV,
    float* __restrict__ Out)
{
    __shared__ float As[16][132];  // [k][m]
    __shared__ float Bs[16][132];  // [k][n]

    const int b   = blockIdx.z;
    const int n0  = blockIdx.x * 128;  // dim tile
    const int tid = threadIdx.x;

    const float* Ab = g_scores + (size_t)b * HEADS * SEQ;  // P: [H][S]
    const float* Bb = KV       + (size_t)b * SEQ * DIM;    // [S][D]

    float acc[8][8];
#pragma unroll
    for (int i = 0; i < 8; i++)
#pragma unroll
        for (int j = 0; j < 8; j++) acc[i][j] = 0.0f;

    const int tm = (tid / 16) * 8;
    const int tn = (tid % 16) * 8;

#pragma unroll 1
    for (int k0 = 0; k0 < SEQ; k0 += 16) {
        // Load A tile: 128 rows (h) x 16 (s), k contiguous, stride SEQ.
#pragma unroll
        for (int l = 0; l < 2; l++) {
            int idx = tid + l * 256;
            int row = idx >> 2;
            int c4  = (idx & 3) * 4;
            float4 v = *reinterpret_cast<const float4*>(
                Ab + (size_t)row * SEQ + k0 + c4);
            As[c4 + 0][row] = v.x;
            As[c4 + 1][row] = v.y;
            As[c4 + 2][row] = v.z;
            As[c4 + 3][row] = v.w;
        }
        // Load B tile: 16 rows (s) x 128 cols (d), n contiguous, stride DIM.
#pragma unroll
        for (int l = 0; l < 2; l++) {
            int idx = tid + l * 256;
            int row = idx >> 5;          // 0..15
            int c4  = (idx & 31) * 4;    // 0..124
            float4 v = *reinterpret_cast<const float4*>(
                Bb + (size_t)(k0 + row) * DIM + n0 + c4);
            *reinterpret_cast<float4*>(&Bs[row][c4]) = v;
        }
        __syncthreads();

#pragma unroll
        for (int k = 0; k < 16; k++) {
            float a[8], bb[8];
            *reinterpret_cast<float4*>(a)      = *reinterpret_cast<const float4*>(&As[k][tm]);
            *reinterpret_cast<float4*>(a + 4)  = *reinterpret_cast<const float4*>(&As[k][tm + 4]);
            *reinterpret_cast<float4*>(bb)     = *reinterpret_cast<const float4*>(&Bs[k][tn]);
            *reinterpret_cast<float4*>(bb + 4) = *reinterpret_cast<const float4*>(&Bs[k][tn + 4]);
#pragma unroll
            for (int i = 0; i < 8; i++)
#pragma unroll
                for (int j = 0; j < 8; j++)
                    acc[i][j] = fmaf(a[i], bb[j], acc[i][j]);
        }
        __syncthreads();
    }

    float* o = Out + (size_t)b * HEADS * DIM;
#pragma unroll
    for (int i = 0; i < 8; i++) {
        float* r = o + (size_t)(tm + i) * DIM + n0 + tn;
        *reinterpret_cast<float4*>(r)     = make_float4(acc[i][0], acc[i][1], acc[i][2], acc[i][3]);
        *reinterpret_cast<float4*>(r + 4) = make_float4(acc[i][4], acc[i][5], acc[i][6], acc[i][7]);
    }
}

// ---------------------------------------------------------------------------
// Launch: Q, Q_pe, KV, K_pe in metadata order; output f32 (64,128,512).
// All launches on the default stream (graph-capturable, no syncs, no allocs).
// ---------------------------------------------------------------------------
extern "C" void kernel_launch(void* const* d_in, const int* in_sizes, int n_in,
                              void* d_out, int out_size)
{
    const float* Q   = (const float*)d_in[0];
    const float* Qpe = (const float*)d_in[1];
    const float* KV  = (const float*)d_in[2];
    const float* Kpe = (const float*)d_in[3];
    float* Out = (float*)d_out;

    dim3 g1(SEQ / 128, 1, BATCH);   // 32 x 64 = 2048 CTAs
    qk_kernel<<<g1, 256>>>(Q, Qpe, KV, Kpe);

    softmax_kernel<<<BATCH * HEADS, 256>>>();

    dim3 g3(DIM / 128, 1, BATCH);   // 4 x 64 = 256 CTAs
    pv_kernel<<<g3, 256>>>(KV, Out);
}

// round 15
// speedup vs baseline: 1.0010x; 1.0010x over previous
#include <cuda_runtime.h>

// Problem constants (fixed shapes from reference)
#define BATCH 64
#define HEADS 128
#define SEQ   4096
#define DIM   512
#define PEDIM 64

// 1/sqrt(576) = 1/24
#define SM_SCALE 0.041666666666666664f

// Scratch for scores/probs: 64*128*4096 floats = 128 MB (static device array,
// allowed per harness rules; cudaMalloc is not).
__device__ float g_scores[(size_t)BATCH * HEADS * SEQ];

// ---------------------------------------------------------------------------
// Kernel 1: scores[b,h,s] = Q[b,h,:]·KV[b,s,:] + Qpe[b,h,:]·Kpe[b,s,:]
// GEMM NT per batch: M=128 (heads), N=4096 (seq), K=576 (512 + 64).
// Tile: BM=128, BN=128, BK=16; 256 threads; 8x8 micro-tile per thread.
// ---------------------------------------------------------------------------
__global__ __launch_bounds__(256, 2) void qk_kernel(
    const float* __restrict__ Q,
    const float* __restrict__ Qpe,
    const float* __restrict__ KV,
    const float* __restrict__ Kpe)
{
    __shared__ float As[16][132];  // [k][m], padded
    __shared__ float Bs[16][132];  // [k][n], padded

    const int b   = blockIdx.z;
    const int n0  = blockIdx.x * 128;
    const int tid = threadIdx.x;

    const float* Aq  = Q   + (size_t)b * HEADS * DIM;
    const float* Ap  = Qpe + (size_t)b * HEADS * PEDIM;
    const float* Bk  = KV  + (size_t)b * SEQ * DIM;
    const float* Bp  = Kpe + (size_t)b * SEQ * PEDIM;

    float acc[8][8];
#pragma unroll
    for (int i = 0; i < 8; i++)
#pragma unroll
        for (int j = 0; j < 8; j++) acc[i][j] = 0.0f;

    const int tm = (tid / 16) * 8;
    const int tn = (tid % 16) * 8;

#pragma unroll 1
    for (int phase = 0; phase < 2; phase++) {
        const float* Aptr = phase ? Ap : Aq;
        const float* Bptr = phase ? Bp : Bk;
        const int kdim = phase ? PEDIM : DIM;

#pragma unroll 1
        for (int k0 = 0; k0 < kdim; k0 += 16) {
            // Load A tile: 128 rows x 16 k (k contiguous). 512 float4, 2/thread.
#pragma unroll
            for (int l = 0; l < 2; l++) {
                int idx = tid + l * 256;
                int row = idx >> 2;
                int c4  = (idx & 3) * 4;
                float4 v = *reinterpret_cast<const float4*>(
                    Aptr + (size_t)row * kdim + k0 + c4);
                As[c4 + 0][row] = v.x;
                As[c4 + 1][row] = v.y;
                As[c4 + 2][row] = v.z;
                As[c4 + 3][row] = v.w;
            }
            // Load B tile: 128 rows (seq) x 16 k (k contiguous).
#pragma unroll
            for (int l = 0; l < 2; l++) {
                int idx = tid + l * 256;
                int row = idx >> 2;
                int c4  = (idx & 3) * 4;
                float4 v = *reinterpret_cast<const float4*>(
                    Bptr + (size_t)(n0 + row) * kdim + k0 + c4);
                Bs[c4 + 0][row] = v.x;
                Bs[c4 + 1][row] = v.y;
                Bs[c4 + 2][row] = v.z;
                Bs[c4 + 3][row] = v.w;
            }
            __syncthreads();

#pragma unroll
            for (int k = 0; k < 16; k++) {
                float a[8], bb[8];
                *reinterpret_cast<float4*>(a)      = *reinterpret_cast<const float4*>(&As[k][tm]);
                *reinterpret_cast<float4*>(a + 4)  = *reinterpret_cast<const float4*>(&As[k][tm + 4]);
                *reinterpret_cast<float4*>(bb)     = *reinterpret_cast<const float4*>(&Bs[k][tn]);
                *reinterpret_cast<float4*>(bb + 4) = *reinterpret_cast<const float4*>(&Bs[k][tn + 4]);
#pragma unroll
                for (int i = 0; i < 8; i++)
#pragma unroll
                    for (int j = 0; j < 8; j++)
                        acc[i][j] = fmaf(a[i], bb[j], acc[i][j]);
            }
            __syncthreads();
        }
    }

    float* out = g_scores + (size_t)b * HEADS * SEQ;
#pragma unroll
    for (int i = 0; i < 8; i++) {
        float* r = out + (size_t)(tm + i) * SEQ + n0 + tn;
        *reinterpret_cast<float4*>(r)     = make_float4(acc[i][0], acc[i][1], acc[i][2], acc[i][3]);
        *reinterpret_cast<float4*>(r + 4) = make_float4(acc[i][4], acc[i][5], acc[i][6], acc[i][7]);
    }
}

// ---------------------------------------------------------------------------
// Kernel 2: in-place row softmax over SEQ (with scale), one block per (b,h).
// Each thread holds 16 values in registers: single read + single write.
// ---------------------------------------------------------------------------
__global__ __launch_bounds__(256) void softmax_kernel()
{
    const size_t row = blockIdx.x;  // b*HEADS + h
    float* p = g_scores + row * SEQ;
    const int tid = threadIdx.x;

    float4 v[4];
#pragma unroll
    for (int it = 0; it < 4; it++)
        v[it] = *reinterpret_cast<const float4*>(p + tid * 4 + it * 1024);

    // --- max ---
    float m = -1e30f;
#pragma unroll
    for (int it = 0; it < 4; it++)
        m = fmaxf(m, fmaxf(fmaxf(v[it].x, v[it].y), fmaxf(v[it].z, v[it].w)));
#pragma unroll
    for (int o = 16; o > 0; o >>= 1)
        m = fmaxf(m, __shfl_xor_sync(0xffffffffu, m, o));

    __shared__ float red[8];
    if ((tid & 31) == 0) red[tid >> 5] = m;
    __syncthreads();
    m = red[0];
#pragma unroll
    for (int i = 1; i < 8; i++) m = fmaxf(m, red[i]);
    __syncthreads();

    // --- exp + sum ---
    float sum = 0.0f;
#pragma unroll
    for (int it = 0; it < 4; it++) {
        v[it].x = expf((v[it].x - m) * SM_SCALE);
        v[it].y = expf((v[it].y - m) * SM_SCALE);
        v[it].z = expf((v[it].z - m) * SM_SCALE);
        v[it].w = expf((v[it].w - m) * SM_SCALE);
        sum += v[it].x + v[it].y + v[it].z + v[it].w;
    }
#pragma unroll
    for (int o = 16; o > 0; o >>= 1)
        sum += __shfl_xor_sync(0xffffffffu, sum, o);

    __shared__ float red2[8];
    if ((tid & 31) == 0) red2[tid >> 5] = sum;
    __syncthreads();
    sum = red2[0];
#pragma unroll
    for (int i = 1; i < 8; i++) sum += red2[i];

    const float inv = 1.0f / sum;
#pragma unroll
    for (int it = 0; it < 4; it++) {
        v[it].x *= inv; v[it].y *= inv; v[it].z *= inv; v[it].w *= inv;
        *reinterpret_cast<float4*>(p + tid * 4 + it * 1024) = v[it];
    }
}

// ---------------------------------------------------------------------------
// Kernel 3: out[b,h,d] = sum_s P[b,h,s] * KV[b,s,d]
// GEMM NN per batch: M=128 (heads), N=512 (dim), K=4096 (seq).
// Same tiling: BM=128, BN=128, BK=16; 256 threads; 8x8 micro-tile.
// ---------------------------------------------------------------------------
__global__ __launch_bounds__(256, 2) void pv_kernel(
    const float* __restrict__ KV,
    float* __restrict__ Out)
{
    __shared__ float As[16][132];  // [k][m]
    __shared__ float Bs[16][132];  // [k][n]

    const int b   = blockIdx.z;
    const int n0  = blockIdx.x * 128;  // dim tile
    const int tid = threadIdx.x;

    const float* Ab = g_scores + (size_t)b * HEADS * SEQ;  // P: [H][S]
    const float* Bb = KV       + (size_t)b * SEQ * DIM;    // [S][D]

    float acc[8][8];
#pragma unroll
    for (int i = 0; i < 8; i++)
#pragma unroll
        for (int j = 0; j < 8; j++) acc[i][j] = 0.0f;

    const int tm = (tid / 16) * 8;
    const int tn = (tid % 16) * 8;

#pragma unroll 1
    for (int k0 = 0; k0 < SEQ; k0 += 16) {
        // Load A tile: 128 rows (h) x 16 (s), k contiguous, stride SEQ.
#pragma unroll
        for (int l = 0; l < 2; l++) {
            int idx = tid + l * 256;
            int row = idx >> 2;
            int c4  = (idx & 3) * 4;
            float4 v = *reinterpret_cast<const float4*>(
                Ab + (size_t)row * SEQ + k0 + c4);
            As[c4 + 0][row] = v.x;
            As[c4 + 1][row] = v.y;
            As[c4 + 2][row] = v.z;
            As[c4 + 3][row] = v.w;
        }
        // Load B tile: 16 rows (s) x 128 cols (d), n contiguous, stride DIM.
#pragma unroll
        for (int l = 0; l < 2; l++) {
            int idx = tid + l * 256;
            int row = idx >> 5;          // 0..15
            int c4  = (idx & 31) * 4;    // 0..124
            float4 v = *reinterpret_cast<const float4*>(
                Bb + (size_t)(k0 + row) * DIM + n0 + c4);
            *reinterpret_cast<float4*>(&Bs[row][c4]) = v;
        }
        __syncthreads();

#pragma unroll
        for (int k = 0; k < 16; k++) {
            float a[8], bb[8];
            *reinterpret_cast<float4*>(a)      = *reinterpret_cast<const float4*>(&As[k][tm]);
            *reinterpret_cast<float4*>(a + 4)  = *reinterpret_cast<const float4*>(&As[k][tm + 4]);
            *reinterpret_cast<float4*>(bb)     = *reinterpret_cast<const float4*>(&Bs[k][tn]);
            *reinterpret_cast<float4*>(bb + 4) = *reinterpret_cast<const float4*>(&Bs[k][tn + 4]);
#pragma unroll
            for (int i = 0; i < 8; i++)
#pragma unroll
                for (int j = 0; j < 8; j++)
                    acc[i][j] = fmaf(a[i], bb[j], acc[i][j]);
        }
        __syncthreads();
    }

    float* o = Out + (size_t)b * HEADS * DIM;
#pragma unroll
    for (int i = 0; i < 8; i++) {
        float* r = o + (size_t)(tm + i) * DIM + n0 + tn;
        *reinterpret_cast<float4*>(r)     = make_float4(acc[i][0], acc[i][1], acc[i][2], acc[i][3]);
        *reinterpret_cast<float4*>(r + 4) = make_float4(acc[i][4], acc[i][5], acc[i][6], acc[i][7]);
    }
}

// ---------------------------------------------------------------------------
// Launch: Q, Q_pe, KV, K_pe in metadata order; output f32 (64,128,512).
// All launches on the default stream (graph-capturable, no syncs, no allocs).
// ---------------------------------------------------------------------------
extern "C" void kernel_launch(void* const* d_in, const int* in_sizes, int n_in,
                              void* d_out, int out_size)
{
    const float* Q   = (const float*)d_in[0];
    const float* Qpe = (const float*)d_in[1];
    const float* KV  = (const float*)d_in[2];
    const float* Kpe = (const float*)d_in[3];
    float* Out = (float*)d_out;

    dim3 g1(SEQ / 128, 1, BATCH);   // 32 x 64 = 2048 CTAs
    qk_kernel<<<g1, 256>>>(Q, Qpe, KV, Kpe);

    softmax_kernel<<<BATCH * HEADS, 256>>>();

    dim3 g3(DIM / 128, 1, BATCH);   // 4 x 64 = 256 CTAs
    pv_kernel<<<g3, 256>>>(KV, Out);
}